// round 10
// baseline (speedup 1.0000x reference)
#include <cuda_runtime.h>
#include <cuda_fp16.h>
#include <math_constants.h>
#include <cstdint>

// Problem constants
#define BB 8
#define TT 2048
#define EE 1024
#define NQKV ((size_t)BB * TT * EE)   // 16,777,216
#define NS   ((size_t)BB * TT * TT)   // 33,554,432

// ---------------------------------------------------------------------------
// Scratch (device globals; allocation forbidden in kernel_launch)
// ---------------------------------------------------------------------------
__device__ __half g_qh[NQKV];                   // q input fp16
__device__ __half g_kh[NQKV];                   // k input fp16
__device__ __half g_vh[NQKV];                   // v input fp16
__device__ __half g_Wqh[EE * EE];               // weights fp16
__device__ __half g_Wkh[EE * EE];
__device__ __half g_Wvh[EE * EE];
__device__ __half g_Qh[NQKV];                   // Q projected
__device__ __half g_Kh[NQKV];                   // K projected
__device__ __half g_Vh[NQKV];                   // V projected
__device__ __half g_VTh[NQKV];                  // V transposed (B in PV)
__device__ float  g_S[NS];                      // scores
__device__ __half g_Ph[NS];                     // softmax weights (A in PV)

// ---------------------------------------------------------------------------
// Helpers
// ---------------------------------------------------------------------------
__device__ __forceinline__ uint32_t smem_u32(const void* p) {
    uint32_t a;
    asm("{ .reg .u64 t; cvta.to.shared.u64 t, %1; cvt.u32.u64 %0, t; }"
        : "=r"(a) : "l"(p));
    return a;
}

__device__ __forceinline__ void cp16(uint32_t dst_smem, const void* src_gmem) {
    asm volatile("cp.async.cg.shared.global [%0], [%1], 16;"
                 :: "r"(dst_smem), "l"(__cvta_generic_to_global(src_gmem)));
}
#define CP_COMMIT() asm volatile("cp.async.commit_group;" ::: "memory")
#define CP_WAIT1()  asm volatile("cp.async.wait_group 1;"  ::: "memory")

// ldmatrix x4 (non-transposed, b16)
__device__ __forceinline__ void ldsm4(uint32_t* r, uint32_t addr) {
    asm volatile("ldmatrix.sync.aligned.m8n8.x4.shared.b16 {%0,%1,%2,%3}, [%4];"
                 : "=r"(r[0]), "=r"(r[1]), "=r"(r[2]), "=r"(r[3]) : "r"(addr));
}

// m16n8k16 fp16 -> fp32 accumulate
__device__ __forceinline__ void mma16816(float* c,
                                         uint32_t a0, uint32_t a1, uint32_t a2, uint32_t a3,
                                         uint32_t b0, uint32_t b1) {
    asm volatile(
        "mma.sync.aligned.m16n8k16.row.col.f32.f16.f16.f32 "
        "{%0,%1,%2,%3}, {%4,%5,%6,%7}, {%8,%9}, {%0,%1,%2,%3};"
        : "+f"(c[0]), "+f"(c[1]), "+f"(c[2]), "+f"(c[3])
        : "r"(a0), "r"(a1), "r"(a2), "r"(a3), "r"(b0), "r"(b1));
}

// ---------------------------------------------------------------------------
// Fused convert: fp32 -> fp16, 3 arrays per launch (z).
// ---------------------------------------------------------------------------
struct CvtArgs {
    const float* src[3];
    __half* dst[3];
    size_t n;
};

__global__ __launch_bounds__(256)
void convert3_kernel(CvtArgs a)
{
    const int z = blockIdx.z;
    const float* __restrict__ x = a.src[z];
    __half* __restrict__ d = a.dst[z];
    const size_t n = a.n;
    const size_t stride = (size_t)gridDim.x * blockDim.x * 8;

    for (size_t i = ((size_t)blockIdx.x * blockDim.x + threadIdx.x) * 8;
         i < n; i += stride) {
#pragma unroll
        for (int w = 0; w < 2; w++) {
            float4 v = *(const float4*)(x + i + w * 4);
            __half2* pd = (__half2*)(d + i + w * 4);
            pd[0] = __halves2half2(__float2half_rn(v.x), __float2half_rn(v.y));
            pd[1] = __halves2half2(__float2half_rn(v.z), __float2half_rn(v.w));
        }
    }
}

// ---------------------------------------------------------------------------
// FP16 NT GEMM on tensor cores (single pass, fp32 accumulate):
//   C[M,N] = alpha * Ah[M,K] * Bh[N,K]^T
// CTA: 128x128xCHUNK, 512 threads = 16 warps (4x4), warp tile 32x32.
// SMEM: 3 stages x 2 tiles (Ah, Bh), each 128 rows x (2*CHUNK+16)B.
// CHUNK=128 preferred (204KB smem); CHUNK=64 fallback (108KB).
// OUT_MODE 0: fp32 C.  2: fp16 Ch.
// Requires M%128==0, N%128==0, K%CHUNK==0.
// ---------------------------------------------------------------------------
template <int CHUNK> struct GemmCfg {
    static constexpr int SROW    = 2 * CHUNK + 16;
    static constexpr int TILE_B  = 128 * SROW;
    static constexpr int STAGE_B = 2 * TILE_B;
    static constexpr int SMEM    = 3 * STAGE_B;
    static constexpr int QPR     = CHUNK / 8;        // 16B quarters per row
    static constexpr int RSTEP   = 512 / QPR;        // rows per copy iter
    static constexpr int JITER   = 128 / RSTEP;      // copy iters per tile
    static constexpr int HBLK    = CHUNK / 16;       // k16 blocks per chunk
};

template <int OUT_MODE, int CHUNK>
__global__ __launch_bounds__(512, 1)
void gemm_f16_nt(const __half* __restrict__ Ah, const __half* __restrict__ Bh,
                 float* __restrict__ C, __half* __restrict__ Ch,
                 int M, int N, int K, float alpha,
                 size_t sA, size_t sB, size_t sC)
{
    using CF = GemmCfg<CHUNK>;
    extern __shared__ __align__(128) char smem[];
    const uint32_t sb = smem_u32(smem);

    const int tid  = threadIdx.x;
    const int wid  = tid >> 5;
    const int lane = tid & 31;
    const int wm   = wid >> 2;          // 0..3  (M: 4 x 32)
    const int wn   = wid & 3;           // 0..3  (N: 4 x 32)
    const int g    = lane >> 2;         // 0..7
    const int i4   = lane & 3;          // 0..3

    const size_t z = blockIdx.z;
    const __half* pAh = Ah + z * sA;
    const __half* pBh = Bh + z * sB;

    const int aRow0 = blockIdx.y * 128;
    const int bRow0 = blockIdx.x * 128;

    // cp.async indices
    const int cr = tid / CF::QPR;        // row base
    const int cq = tid % CF::QPR;        // 16B quarter

    // ldmatrix per-lane address offsets (warp tile 32x32)
    const int lmA = lane & 15;
    const int lqA = (lane >> 4) & 1;
    uint32_t aoff[2];
#pragma unroll
    for (int fm = 0; fm < 2; fm++)
        aoff[fm] = (uint32_t)((wm * 32 + fm * 16 + lmA) * CF::SROW + lqA * 16);
    const int bn = (lane & 7) + ((lane >> 4) << 3);
    const int bq = (lane >> 3) & 1;
    uint32_t boff[2];
#pragma unroll
    for (int fp = 0; fp < 2; fp++)
        boff[fp] = (uint32_t)((wn * 32 + fp * 16 + bn) * CF::SROW + bq * 16);

    float acc[2][4][4];
#pragma unroll
    for (int a = 0; a < 2; a++)
#pragma unroll
        for (int b = 0; b < 4; b++)
#pragma unroll
            for (int c = 0; c < 4; c++) acc[a][b][c] = 0.0f;

    const int nch = K / CHUNK;

    auto issue = [&](int kc) {
        const uint32_t tb = sb + (uint32_t)(kc % 3) * CF::STAGE_B;
        const int kofs = kc * CHUNK;
#pragma unroll
        for (int j = 0; j < CF::JITER; j++) {
            const int r = cr + j * CF::RSTEP;
            const uint32_t so = (uint32_t)(r * CF::SROW + cq * 16);
            cp16(tb + 0 * CF::TILE_B + so,
                 pAh + (size_t)(aRow0 + r) * K + kofs + cq * 8);
            cp16(tb + 1 * CF::TILE_B + so,
                 pBh + (size_t)(bRow0 + r) * K + kofs + cq * 8);
        }
        CP_COMMIT();
    };

    issue(0);
    issue(1);

    for (int kc = 0; kc < nch; kc++) {
        CP_WAIT1();
        __syncthreads();
        if (kc + 2 < nch) issue(kc + 2);

        const uint32_t tb = sb + (uint32_t)(kc % 3) * CF::STAGE_B;
#pragma unroll
        for (int h = 0; h < CF::HBLK; h++) {
            const uint32_t ho = (uint32_t)(h * 32);
            uint32_t ah[2][4];
#pragma unroll
            for (int fm = 0; fm < 2; fm++)
                ldsm4(ah[fm], tb + 0 * CF::TILE_B + aoff[fm] + ho);
            uint32_t bh[2][4];
#pragma unroll
            for (int fp = 0; fp < 2; fp++)
                ldsm4(bh[fp], tb + 1 * CF::TILE_B + boff[fp] + ho);
#pragma unroll
            for (int fn = 0; fn < 4; fn++) {
                const uint32_t b0 = bh[fn >> 1][(fn & 1) * 2];
                const uint32_t b1 = bh[fn >> 1][(fn & 1) * 2 + 1];
#pragma unroll
                for (int fm = 0; fm < 2; fm++)
                    mma16816(acc[fm][fn], ah[fm][0], ah[fm][1], ah[fm][2], ah[fm][3], b0, b1);
            }
        }
    }

    // Epilogue
    const int rowB = aRow0 + wm * 32 + g;
    const int colB = bRow0 + wn * 32 + i4 * 2;
#pragma unroll
    for (int fm = 0; fm < 2; fm++) {
#pragma unroll
        for (int fn = 0; fn < 4; fn++) {
            const int row = rowB + fm * 16;
            const int col = colB + fn * 8;
            const float c0 = alpha * acc[fm][fn][0];
            const float c1 = alpha * acc[fm][fn][1];
            const float c2 = alpha * acc[fm][fn][2];
            const float c3 = alpha * acc[fm][fn][3];
            if (OUT_MODE == 0) {
                float* pc = C + z * sC;
                *(float2*)(pc + (size_t)row * N + col)       = make_float2(c0, c1);
                *(float2*)(pc + (size_t)(row + 8) * N + col) = make_float2(c2, c3);
            } else {
                __half* ph = Ch + z * sC;
                *(__half2*)(ph + (size_t)row * N + col) =
                    __halves2half2(__float2half_rn(c0), __float2half_rn(c1));
                *(__half2*)(ph + (size_t)(row + 8) * N + col) =
                    __halves2half2(__float2half_rn(c2), __float2half_rn(c3));
            }
        }
    }
}

// ---------------------------------------------------------------------------
// Transpose fp16: V[b][s][o] -> VT[b][o][s] (32x32 tiles)
// ---------------------------------------------------------------------------
__global__ __launch_bounds__(256)
void transpose_h_kernel(const __half* __restrict__ V, __half* __restrict__ T)
{
    __shared__ uint16_t t[32][34];
    const int b  = blockIdx.z;
    const int s0 = blockIdx.x << 5;
    const int o0 = blockIdx.y << 5;
    const __half* Vb = V + (size_t)b * TT * EE;
    __half* Tb = T + (size_t)b * EE * TT;
    const int tx = threadIdx.x & 31;
    const int ty = threadIdx.x >> 5;
#pragma unroll
    for (int i = 0; i < 4; i++)
        t[ty + 8 * i][tx] = __half_as_ushort(Vb[(size_t)(s0 + ty + 8 * i) * EE + o0 + tx]);
    __syncthreads();
#pragma unroll
    for (int i = 0; i < 4; i++)
        Tb[(size_t)(o0 + ty + 8 * i) * TT + s0 + tx] = __ushort_as_half(t[tx][ty + 8 * i]);
}

// ---------------------------------------------------------------------------
// Masked row softmax: S[B*T, T] fp32 -> fp16 P. mask 0 -> -inf.
// ---------------------------------------------------------------------------
__global__ __launch_bounds__(256)
void softmax_h_kernel(const float* __restrict__ S, const int* __restrict__ mask,
                      __half* __restrict__ Ph)
{
    const int row = blockIdx.x;
    const int t   = row & (TT - 1);
    const float* Srow = S + (size_t)row * TT;
    const int* mrow = mask + (size_t)t * TT;
    const int tid = threadIdx.x;

    float v[8];
    float m = -CUDART_INF_F;
#pragma unroll
    for (int i = 0; i < 8; i++) {
        int s = tid + i * 256;
        float x = (mrow[s] != 0) ? Srow[s] : -CUDART_INF_F;
        v[i] = x;
        m = fmaxf(m, x);
    }

    __shared__ float red[256];
    red[tid] = m;
    __syncthreads();
    for (int off = 128; off > 0; off >>= 1) {
        if (tid < off) red[tid] = fmaxf(red[tid], red[tid + off]);
        __syncthreads();
    }
    m = red[0];
    __syncthreads();

    float sum = 0.0f;
#pragma unroll
    for (int i = 0; i < 8; i++) {
        float e = __expf(v[i] - m);
        v[i] = e;
        sum += e;
    }
    red[tid] = sum;
    __syncthreads();
    for (int off = 128; off > 0; off >>= 1) {
        if (tid < off) red[tid] += red[tid + off];
        __syncthreads();
    }
    const float inv = 1.0f / red[0];

    __half* Phr = Ph + (size_t)row * TT;
#pragma unroll
    for (int i = 0; i < 8; i++)
        Phr[tid + i * 256] = __float2half_rn(v[i] * inv);
}

// ---------------------------------------------------------------------------
// kernel_launch
// Order: 1 convert3(q,k,v)  2 convert3(W)  3 projQ  4 projK  5 projV
//        6 scores GEMM      7 transpose    8 softmax  9 PV GEMM
// ---------------------------------------------------------------------------
extern "C" void kernel_launch(void* const* d_in, const int* in_sizes, int n_in,
                              void* d_out, int out_size)
{
    const float* q    = (const float*)d_in[0];
    const float* k    = (const float*)d_in[1];
    const float* v    = (const float*)d_in[2];
    const int*   mask = (const int*)  d_in[3];
    const float* Wq   = (const float*)d_in[4];
    const float* Wk   = (const float*)d_in[5];
    const float* Wv   = (const float*)d_in[6];
    float* out = (float*)d_out;

    __half *qh, *kh, *vh, *wqh, *wkh, *wvh;
    __half *Qh, *Kh, *Vh, *VTh, *Ph;
    float *S;
    cudaGetSymbolAddress((void**)&qh,  g_qh);
    cudaGetSymbolAddress((void**)&kh,  g_kh);
    cudaGetSymbolAddress((void**)&vh,  g_vh);
    cudaGetSymbolAddress((void**)&wqh, g_Wqh);
    cudaGetSymbolAddress((void**)&wkh, g_Wkh);
    cudaGetSymbolAddress((void**)&wvh, g_Wvh);
    cudaGetSymbolAddress((void**)&Qh,  g_Qh);
    cudaGetSymbolAddress((void**)&Kh,  g_Kh);
    cudaGetSymbolAddress((void**)&Vh,  g_Vh);
    cudaGetSymbolAddress((void**)&VTh, g_VTh);
    cudaGetSymbolAddress((void**)&Ph,  g_Ph);
    cudaGetSymbolAddress((void**)&S,   g_S);

    // Prefer CHUNK=128 (204KB smem); fall back to CHUNK=64 if rejected.
    const int SM128 = GemmCfg<128>::SMEM;
    const int SM64  = GemmCfg<64>::SMEM;
    bool big = true;
    if (cudaFuncSetAttribute((const void*)gemm_f16_nt<0, 128>,
            cudaFuncAttributeMaxDynamicSharedMemorySize, SM128) != cudaSuccess) big = false;
    if (cudaFuncSetAttribute((const void*)gemm_f16_nt<2, 128>,
            cudaFuncAttributeMaxDynamicSharedMemorySize, SM128) != cudaSuccess) big = false;
    cudaFuncSetAttribute((const void*)gemm_f16_nt<0, 64>,
        cudaFuncAttributeMaxDynamicSharedMemorySize, SM64);
    cudaFuncSetAttribute((const void*)gemm_f16_nt<2, 64>,
        cudaFuncAttributeMaxDynamicSharedMemorySize, SM64);
    cudaGetLastError();   // clear any sticky attribute error

    const int M = BB * TT;                   // 16384
    const size_t strQKV = (size_t)TT * EE;
    const size_t strS   = (size_t)TT * TT;
    const size_t strVT  = (size_t)EE * TT;

    // 1) Convert q,k,v inputs to fp16
    {
        CvtArgs a;
        a.src[0] = q;  a.src[1] = k;  a.src[2] = v;
        a.dst[0] = qh; a.dst[1] = kh; a.dst[2] = vh;
        a.n = NQKV;
        dim3 gs((unsigned)(NQKV / (256 * 8)), 1, 3);
        convert3_kernel<<<gs, 256>>>(a);
    }
    // 2) Convert weights to fp16
    {
        CvtArgs a;
        a.src[0] = Wq;  a.src[1] = Wk;  a.src[2] = Wv;
        a.dst[0] = wqh; a.dst[1] = wkh; a.dst[2] = wvh;
        a.n = (size_t)EE * EE;
        dim3 gs((unsigned)((size_t)EE * EE / (256 * 8)), 1, 3);
        convert3_kernel<<<gs, 256>>>(a);
    }

    dim3 gProj(EE / 128, M / 128, 1);
    dim3 gScore(TT / 128, TT / 128, BB);
    dim3 gOut(EE / 128, TT / 128, BB);
    dim3 gT(TT / 32, EE / 32, BB);

    if (big) {
        // 3-5) Projections -> fp16
        gemm_f16_nt<2, 128><<<gProj, 512, SM128>>>(qh, wqh, nullptr, Qh,
            M, EE, EE, 1.0f, 0, 0, 0);
        gemm_f16_nt<2, 128><<<gProj, 512, SM128>>>(kh, wkh, nullptr, Kh,
            M, EE, EE, 1.0f, 0, 0, 0);
        gemm_f16_nt<2, 128><<<gProj, 512, SM128>>>(vh, wvh, nullptr, Vh,
            M, EE, EE, 1.0f, 0, 0, 0);
        // 6) Scores -> fp32
        gemm_f16_nt<0, 128><<<gScore, 512, SM128>>>(Qh, Kh, S, nullptr,
            TT, TT, EE, 1.0f / 32.0f, strQKV, strQKV, strS);
        // 7) Transpose V
        transpose_h_kernel<<<gT, 256>>>(Vh, VTh);
        // 8) Softmax -> fp16 P
        softmax_h_kernel<<<BB * TT, 256>>>(S, mask, Ph);
        // 9) PV -> fp32 out
        gemm_f16_nt<0, 128><<<gOut, 512, SM128>>>(Ph, VTh, out, nullptr,
            TT, EE, TT, 1.0f, strS, strVT, strQKV);
    } else {
        gemm_f16_nt<2, 64><<<gProj, 512, SM64>>>(qh, wqh, nullptr, Qh,
            M, EE, EE, 1.0f, 0, 0, 0);
        gemm_f16_nt<2, 64><<<gProj, 512, SM64>>>(kh, wkh, nullptr, Kh,
            M, EE, EE, 1.0f, 0, 0, 0);
        gemm_f16_nt<2, 64><<<gProj, 512, SM64>>>(vh, wvh, nullptr, Vh,
            M, EE, EE, 1.0f, 0, 0, 0);
        gemm_f16_nt<0, 64><<<gScore, 512, SM64>>>(Qh, Kh, S, nullptr,
            TT, TT, EE, 1.0f / 32.0f, strQKV, strQKV, strS);
        transpose_h_kernel<<<gT, 256>>>(Vh, VTh);
        softmax_h_kernel<<<BB * TT, 256>>>(S, mask, Ph);
        gemm_f16_nt<0, 64><<<gOut, 512, SM64>>>(Ph, VTh, out, nullptr,
            TT, EE, TT, 1.0f, strS, strVT, strQKV);
    }
}

// round 11
// speedup vs baseline: 1.0056x; 1.0056x over previous
#include <cuda_runtime.h>
#include <cuda_fp16.h>
#include <math_constants.h>
#include <cstdint>

// Problem constants
#define BB 8
#define TT 2048
#define EE 1024
#define NQKV ((size_t)BB * TT * EE)   // 16,777,216
#define NS   ((size_t)BB * TT * TT)   // 33,554,432

// ---------------------------------------------------------------------------
// Scratch (device globals; allocation forbidden in kernel_launch)
// ---------------------------------------------------------------------------
__device__ __half g_qh[NQKV];                   // q input fp16
__device__ __half g_kh[NQKV];                   // k input fp16
__device__ __half g_vh[NQKV];                   // v input fp16
__device__ __half g_Wqh[EE * EE];               // weights fp16
__device__ __half g_Wkh[EE * EE];
__device__ __half g_Wvh[EE * EE];
__device__ __half g_Qh[NQKV];                   // Q projected
__device__ __half g_Kh[NQKV];                   // K projected
__device__ __half g_Vh[NQKV];                   // V projected
__device__ __half g_VTh[NQKV];                  // V transposed (B in PV)
__device__ float  g_S[NS];                      // scores
__device__ __half g_Ph[NS];                     // softmax weights (A in PV)

// ---------------------------------------------------------------------------
// Helpers
// ---------------------------------------------------------------------------
__device__ __forceinline__ uint32_t smem_u32(const void* p) {
    uint32_t a;
    asm("{ .reg .u64 t; cvta.to.shared.u64 t, %1; cvt.u32.u64 %0, t; }"
        : "=r"(a) : "l"(p));
    return a;
}

__device__ __forceinline__ void cp16(uint32_t dst_smem, const void* src_gmem) {
    asm volatile("cp.async.cg.shared.global [%0], [%1], 16;"
                 :: "r"(dst_smem), "l"(__cvta_generic_to_global(src_gmem)));
}
#define CP_COMMIT() asm volatile("cp.async.commit_group;" ::: "memory")
#define CP_WAIT1()  asm volatile("cp.async.wait_group 1;"  ::: "memory")

// ldmatrix x4 (non-transposed, b16)
__device__ __forceinline__ void ldsm4(uint32_t* r, uint32_t addr) {
    asm volatile("ldmatrix.sync.aligned.m8n8.x4.shared.b16 {%0,%1,%2,%3}, [%4];"
                 : "=r"(r[0]), "=r"(r[1]), "=r"(r[2]), "=r"(r[3]) : "r"(addr));
}

// m16n8k16 fp16 -> fp32 accumulate
__device__ __forceinline__ void mma16816(float* c,
                                         uint32_t a0, uint32_t a1, uint32_t a2, uint32_t a3,
                                         uint32_t b0, uint32_t b1) {
    asm volatile(
        "mma.sync.aligned.m16n8k16.row.col.f32.f16.f16.f32 "
        "{%0,%1,%2,%3}, {%4,%5,%6,%7}, {%8,%9}, {%0,%1,%2,%3};"
        : "+f"(c[0]), "+f"(c[1]), "+f"(c[2]), "+f"(c[3])
        : "r"(a0), "r"(a1), "r"(a2), "r"(a3), "r"(b0), "r"(b1));
}

// ---------------------------------------------------------------------------
// Fused convert: fp32 -> fp16, 3 arrays per launch (z).
// ---------------------------------------------------------------------------
struct CvtArgs {
    const float* src[3];
    __half* dst[3];
    size_t n;
};

__global__ __launch_bounds__(256)
void convert3_kernel(CvtArgs a)
{
    const int z = blockIdx.z;
    const float* __restrict__ x = a.src[z];
    __half* __restrict__ d = a.dst[z];
    const size_t n = a.n;
    const size_t stride = (size_t)gridDim.x * blockDim.x * 8;

    for (size_t i = ((size_t)blockIdx.x * blockDim.x + threadIdx.x) * 8;
         i < n; i += stride) {
#pragma unroll
        for (int w = 0; w < 2; w++) {
            float4 v = *(const float4*)(x + i + w * 4);
            __half2* pd = (__half2*)(d + i + w * 4);
            pd[0] = __halves2half2(__float2half_rn(v.x), __float2half_rn(v.y));
            pd[1] = __halves2half2(__float2half_rn(v.z), __float2half_rn(v.w));
        }
    }
}

// ---------------------------------------------------------------------------
// FP16 NT GEMM on tensor cores (single pass, fp32 accumulate):
//   C[M,N] = alpha * Ah[M,K] * Bh[N,K]^T
// CTA: 128x128xCHUNK, 512 threads = 16 warps (4x4), warp tile 32x32.
// Register-pipelined fragments: ldsm for h+1 issued before HMMA of h.
// SMEM: 3 stages x 2 tiles, each 128 rows x (2*CHUNK+16)B.
// CHUNK=128 preferred (204KB smem); CHUNK=64 fallback (108KB).
// OUT_MODE 0: fp32 C.  2: fp16 Ch.
// Requires M%128==0, N%128==0, K%CHUNK==0.
// ---------------------------------------------------------------------------
template <int CHUNK> struct GemmCfg {
    static constexpr int SROW    = 2 * CHUNK + 16;
    static constexpr int TILE_B  = 128 * SROW;
    static constexpr int STAGE_B = 2 * TILE_B;
    static constexpr int SMEM    = 3 * STAGE_B;
    static constexpr int QPR     = CHUNK / 8;        // 16B quarters per row
    static constexpr int RSTEP   = 512 / QPR;        // rows per copy iter
    static constexpr int JITER   = 128 / RSTEP;      // copy iters per tile
    static constexpr int HBLK    = CHUNK / 16;       // k16 blocks per chunk
};

template <int OUT_MODE, int CHUNK>
__global__ __launch_bounds__(512, 1)
void gemm_f16_nt(const __half* __restrict__ Ah, const __half* __restrict__ Bh,
                 float* __restrict__ C, __half* __restrict__ Ch,
                 int M, int N, int K, float alpha,
                 size_t sA, size_t sB, size_t sC)
{
    using CF = GemmCfg<CHUNK>;
    extern __shared__ __align__(128) char smem[];
    const uint32_t sb = smem_u32(smem);

    const int tid  = threadIdx.x;
    const int wid  = tid >> 5;
    const int lane = tid & 31;
    const int wm   = wid >> 2;          // 0..3  (M: 4 x 32)
    const int wn   = wid & 3;           // 0..3  (N: 4 x 32)
    const int g    = lane >> 2;         // 0..7
    const int i4   = lane & 3;          // 0..3

    const size_t z = blockIdx.z;
    const __half* pAh = Ah + z * sA;
    const __half* pBh = Bh + z * sB;

    const int aRow0 = blockIdx.y * 128;
    const int bRow0 = blockIdx.x * 128;

    // cp.async indices
    const int cr = tid / CF::QPR;        // row base
    const int cq = tid % CF::QPR;        // 16B quarter

    // ldmatrix per-lane address offsets (warp tile 32x32)
    const int lmA = lane & 15;
    const int lqA = (lane >> 4) & 1;
    uint32_t aoff[2];
#pragma unroll
    for (int fm = 0; fm < 2; fm++)
        aoff[fm] = (uint32_t)((wm * 32 + fm * 16 + lmA) * CF::SROW + lqA * 16);
    const int bn = (lane & 7) + ((lane >> 4) << 3);
    const int bq = (lane >> 3) & 1;
    uint32_t boff[2];
#pragma unroll
    for (int fp = 0; fp < 2; fp++)
        boff[fp] = (uint32_t)((wn * 32 + fp * 16 + bn) * CF::SROW + bq * 16);

    float acc[2][4][4];
#pragma unroll
    for (int a = 0; a < 2; a++)
#pragma unroll
        for (int b = 0; b < 4; b++)
#pragma unroll
            for (int c = 0; c < 4; c++) acc[a][b][c] = 0.0f;

    const int nch = K / CHUNK;

    auto issue = [&](int kc) {
        const uint32_t tb = sb + (uint32_t)(kc % 3) * CF::STAGE_B;
        const int kofs = kc * CHUNK;
#pragma unroll
        for (int j = 0; j < CF::JITER; j++) {
            const int r = cr + j * CF::RSTEP;
            const uint32_t so = (uint32_t)(r * CF::SROW + cq * 16);
            cp16(tb + 0 * CF::TILE_B + so,
                 pAh + (size_t)(aRow0 + r) * K + kofs + cq * 8);
            cp16(tb + 1 * CF::TILE_B + so,
                 pBh + (size_t)(bRow0 + r) * K + kofs + cq * 8);
        }
        CP_COMMIT();
    };

    issue(0);
    issue(1);

    // Double-buffered register fragments (a: 2 frags, b: 2 frags per h)
    uint32_t ar[2][2][4], br[2][2][4];

    for (int kc = 0; kc < nch; kc++) {
        CP_WAIT1();
        __syncthreads();
        if (kc + 2 < nch) issue(kc + 2);

        const uint32_t tb = sb + (uint32_t)(kc % 3) * CF::STAGE_B;

        // Prologue: load fragments for h = 0
        ldsm4(ar[0][0], tb + 0 * CF::TILE_B + aoff[0]);
        ldsm4(ar[0][1], tb + 0 * CF::TILE_B + aoff[1]);
        ldsm4(br[0][0], tb + 1 * CF::TILE_B + boff[0]);
        ldsm4(br[0][1], tb + 1 * CF::TILE_B + boff[1]);

#pragma unroll
        for (int h = 0; h < CF::HBLK; h++) {
            const int cur = h & 1;
            const int nxt = cur ^ 1;
            // Prefetch next h's fragments before issuing HMMA of current h
            if (h + 1 < CF::HBLK) {
                const uint32_t ho = (uint32_t)((h + 1) * 32);
                ldsm4(ar[nxt][0], tb + 0 * CF::TILE_B + aoff[0] + ho);
                ldsm4(ar[nxt][1], tb + 0 * CF::TILE_B + aoff[1] + ho);
                ldsm4(br[nxt][0], tb + 1 * CF::TILE_B + boff[0] + ho);
                ldsm4(br[nxt][1], tb + 1 * CF::TILE_B + boff[1] + ho);
            }
#pragma unroll
            for (int fn = 0; fn < 4; fn++) {
                const uint32_t b0 = br[cur][fn >> 1][(fn & 1) * 2];
                const uint32_t b1 = br[cur][fn >> 1][(fn & 1) * 2 + 1];
#pragma unroll
                for (int fm = 0; fm < 2; fm++)
                    mma16816(acc[fm][fn], ar[cur][fm][0], ar[cur][fm][1],
                             ar[cur][fm][2], ar[cur][fm][3], b0, b1);
            }
        }
    }

    // Epilogue
    const int rowB = aRow0 + wm * 32 + g;
    const int colB = bRow0 + wn * 32 + i4 * 2;
#pragma unroll
    for (int fm = 0; fm < 2; fm++) {
#pragma unroll
        for (int fn = 0; fn < 4; fn++) {
            const int row = rowB + fm * 16;
            const int col = colB + fn * 8;
            const float c0 = alpha * acc[fm][fn][0];
            const float c1 = alpha * acc[fm][fn][1];
            const float c2 = alpha * acc[fm][fn][2];
            const float c3 = alpha * acc[fm][fn][3];
            if (OUT_MODE == 0) {
                float* pc = C + z * sC;
                *(float2*)(pc + (size_t)row * N + col)       = make_float2(c0, c1);
                *(float2*)(pc + (size_t)(row + 8) * N + col) = make_float2(c2, c3);
            } else {
                __half* ph = Ch + z * sC;
                *(__half2*)(ph + (size_t)row * N + col) =
                    __halves2half2(__float2half_rn(c0), __float2half_rn(c1));
                *(__half2*)(ph + (size_t)(row + 8) * N + col) =
                    __halves2half2(__float2half_rn(c2), __float2half_rn(c3));
            }
        }
    }
}

// ---------------------------------------------------------------------------
// Transpose fp16: V[b][s][o] -> VT[b][o][s] (32x32 tiles)
// ---------------------------------------------------------------------------
__global__ __launch_bounds__(256)
void transpose_h_kernel(const __half* __restrict__ V, __half* __restrict__ T)
{
    __shared__ uint16_t t[32][34];
    const int b  = blockIdx.z;
    const int s0 = blockIdx.x << 5;
    const int o0 = blockIdx.y << 5;
    const __half* Vb = V + (size_t)b * TT * EE;
    __half* Tb = T + (size_t)b * EE * TT;
    const int tx = threadIdx.x & 31;
    const int ty = threadIdx.x >> 5;
#pragma unroll
    for (int i = 0; i < 4; i++)
        t[ty + 8 * i][tx] = __half_as_ushort(Vb[(size_t)(s0 + ty + 8 * i) * EE + o0 + tx]);
    __syncthreads();
#pragma unroll
    for (int i = 0; i < 4; i++)
        Tb[(size_t)(o0 + ty + 8 * i) * TT + s0 + tx] = __ushort_as_half(t[tx][ty + 8 * i]);
}

// ---------------------------------------------------------------------------
// Masked row softmax: S[B*T, T] fp32 -> fp16 P. mask 0 -> -inf.
// ---------------------------------------------------------------------------
__global__ __launch_bounds__(256)
void softmax_h_kernel(const float* __restrict__ S, const int* __restrict__ mask,
                      __half* __restrict__ Ph)
{
    const int row = blockIdx.x;
    const int t   = row & (TT - 1);
    const float* Srow = S + (size_t)row * TT;
    const int* mrow = mask + (size_t)t * TT;
    const int tid = threadIdx.x;

    float v[8];
    float m = -CUDART_INF_F;
#pragma unroll
    for (int i = 0; i < 8; i++) {
        int s = tid + i * 256;
        float x = (mrow[s] != 0) ? Srow[s] : -CUDART_INF_F;
        v[i] = x;
        m = fmaxf(m, x);
    }

    __shared__ float red[256];
    red[tid] = m;
    __syncthreads();
    for (int off = 128; off > 0; off >>= 1) {
        if (tid < off) red[tid] = fmaxf(red[tid], red[tid + off]);
        __syncthreads();
    }
    m = red[0];
    __syncthreads();

    float sum = 0.0f;
#pragma unroll
    for (int i = 0; i < 8; i++) {
        float e = __expf(v[i] - m);
        v[i] = e;
        sum += e;
    }
    red[tid] = sum;
    __syncthreads();
    for (int off = 128; off > 0; off >>= 1) {
        if (tid < off) red[tid] += red[tid + off];
        __syncthreads();
    }
    const float inv = 1.0f / red[0];

    __half* Phr = Ph + (size_t)row * TT;
#pragma unroll
    for (int i = 0; i < 8; i++)
        Phr[tid + i * 256] = __float2half_rn(v[i] * inv);
}

// ---------------------------------------------------------------------------
// kernel_launch
// Order: 1 convert3(q,k,v)  2 convert3(W)  3 projQ  4 projK  5 projV
//        6 scores GEMM      7 transpose    8 softmax  9 PV GEMM
// ---------------------------------------------------------------------------
extern "C" void kernel_launch(void* const* d_in, const int* in_sizes, int n_in,
                              void* d_out, int out_size)
{
    const float* q    = (const float*)d_in[0];
    const float* k    = (const float*)d_in[1];
    const float* v    = (const float*)d_in[2];
    const int*   mask = (const int*)  d_in[3];
    const float* Wq   = (const float*)d_in[4];
    const float* Wk   = (const float*)d_in[5];
    const float* Wv   = (const float*)d_in[6];
    float* out = (float*)d_out;

    __half *qh, *kh, *vh, *wqh, *wkh, *wvh;
    __half *Qh, *Kh, *Vh, *VTh, *Ph;
    float *S;
    cudaGetSymbolAddress((void**)&qh,  g_qh);
    cudaGetSymbolAddress((void**)&kh,  g_kh);
    cudaGetSymbolAddress((void**)&vh,  g_vh);
    cudaGetSymbolAddress((void**)&wqh, g_Wqh);
    cudaGetSymbolAddress((void**)&wkh, g_Wkh);
    cudaGetSymbolAddress((void**)&wvh, g_Wvh);
    cudaGetSymbolAddress((void**)&Qh,  g_Qh);
    cudaGetSymbolAddress((void**)&Kh,  g_Kh);
    cudaGetSymbolAddress((void**)&Vh,  g_Vh);
    cudaGetSymbolAddress((void**)&VTh, g_VTh);
    cudaGetSymbolAddress((void**)&Ph,  g_Ph);
    cudaGetSymbolAddress((void**)&S,   g_S);

    // Prefer CHUNK=128 (204KB smem); fall back to CHUNK=64 if rejected.
    const int SM128 = GemmCfg<128>::SMEM;
    const int SM64  = GemmCfg<64>::SMEM;
    bool big = true;
    if (cudaFuncSetAttribute((const void*)gemm_f16_nt<0, 128>,
            cudaFuncAttributeMaxDynamicSharedMemorySize, SM128) != cudaSuccess) big = false;
    if (cudaFuncSetAttribute((const void*)gemm_f16_nt<2, 128>,
            cudaFuncAttributeMaxDynamicSharedMemorySize, SM128) != cudaSuccess) big = false;
    cudaFuncSetAttribute((const void*)gemm_f16_nt<0, 64>,
        cudaFuncAttributeMaxDynamicSharedMemorySize, SM64);
    cudaFuncSetAttribute((const void*)gemm_f16_nt<2, 64>,
        cudaFuncAttributeMaxDynamicSharedMemorySize, SM64);
    cudaGetLastError();   // clear any sticky attribute error

    const int M = BB * TT;                   // 16384
    const size_t strQKV = (size_t)TT * EE;
    const size_t strS   = (size_t)TT * TT;
    const size_t strVT  = (size_t)EE * TT;

    // 1) Convert q,k,v inputs to fp16
    {
        CvtArgs a;
        a.src[0] = q;  a.src[1] = k;  a.src[2] = v;
        a.dst[0] = qh; a.dst[1] = kh; a.dst[2] = vh;
        a.n = NQKV;
        dim3 gs((unsigned)(NQKV / (256 * 8)), 1, 3);
        convert3_kernel<<<gs, 256>>>(a);
    }
    // 2) Convert weights to fp16
    {
        CvtArgs a;
        a.src[0] = Wq;  a.src[1] = Wk;  a.src[2] = Wv;
        a.dst[0] = wqh; a.dst[1] = wkh; a.dst[2] = wvh;
        a.n = (size_t)EE * EE;
        dim3 gs((unsigned)((size_t)EE * EE / (256 * 8)), 1, 3);
        convert3_kernel<<<gs, 256>>>(a);
    }

    dim3 gProj(EE / 128, M / 128, 1);
    dim3 gScore(TT / 128, TT / 128, BB);
    dim3 gOut(EE / 128, TT / 128, BB);
    dim3 gT(TT / 32, EE / 32, BB);

    if (big) {
        gemm_f16_nt<2, 128><<<gProj, 512, SM128>>>(qh, wqh, nullptr, Qh,
            M, EE, EE, 1.0f, 0, 0, 0);
        gemm_f16_nt<2, 128><<<gProj, 512, SM128>>>(kh, wkh, nullptr, Kh,
            M, EE, EE, 1.0f, 0, 0, 0);
        gemm_f16_nt<2, 128><<<gProj, 512, SM128>>>(vh, wvh, nullptr, Vh,
            M, EE, EE, 1.0f, 0, 0, 0);
        gemm_f16_nt<0, 128><<<gScore, 512, SM128>>>(Qh, Kh, S, nullptr,
            TT, TT, EE, 1.0f / 32.0f, strQKV, strQKV, strS);
        transpose_h_kernel<<<gT, 256>>>(Vh, VTh);
        softmax_h_kernel<<<BB * TT, 256>>>(S, mask, Ph);
        gemm_f16_nt<0, 128><<<gOut, 512, SM128>>>(Ph, VTh, out, nullptr,
            TT, EE, TT, 1.0f, strS, strVT, strQKV);
    } else {
        gemm_f16_nt<2, 64><<<gProj, 512, SM64>>>(qh, wqh, nullptr, Qh,
            M, EE, EE, 1.0f, 0, 0, 0);
        gemm_f16_nt<2, 64><<<gProj, 512, SM64>>>(kh, wkh, nullptr, Kh,
            M, EE, EE, 1.0f, 0, 0, 0);
        gemm_f16_nt<2, 64><<<gProj, 512, SM64>>>(vh, wvh, nullptr, Vh,
            M, EE, EE, 1.0f, 0, 0, 0);
        gemm_f16_nt<0, 64><<<gScore, 512, SM64>>>(Qh, Kh, S, nullptr,
            TT, TT, EE, 1.0f / 32.0f, strQKV, strQKV, strS);
        transpose_h_kernel<<<gT, 256>>>(Vh, VTh);
        softmax_h_kernel<<<BB * TT, 256>>>(S, mask, Ph);
        gemm_f16_nt<0, 64><<<gOut, 512, SM64>>>(Ph, VTh, out, nullptr,
            TT, EE, TT, 1.0f, strS, strVT, strQKV);
    }
}

// round 12
// speedup vs baseline: 1.2287x; 1.2219x over previous
#include <cuda_runtime.h>
#include <cuda_fp16.h>
#include <math_constants.h>
#include <cstdint>

// Problem constants
#define BB 8
#define TT 2048
#define EE 1024
#define NQKV ((size_t)BB * TT * EE)   // 16,777,216
#define NS   ((size_t)BB * TT * TT)   // 33,554,432

// ---------------------------------------------------------------------------
// Scratch (device globals; allocation forbidden in kernel_launch)
// ---------------------------------------------------------------------------
__device__ __half g_qh[NQKV];                   // q input fp16
__device__ __half g_kh[NQKV];                   // k input fp16
__device__ __half g_vh[NQKV];                   // v input fp16
__device__ __half g_Wqh[EE * EE];               // weights fp16
__device__ __half g_Wkh[EE * EE];
__device__ __half g_Wvh[EE * EE];
__device__ __half g_Qh[NQKV];                   // Q projected
__device__ __half g_Kh[NQKV];                   // K projected
__device__ __half g_Vh[NQKV];                   // V projected
__device__ __half g_VTh[NQKV];                  // V transposed (B in PV)
__device__ float  g_S[NS];                      // scores
__device__ __half g_Ph[NS];                     // softmax weights (A in PV)

// ---------------------------------------------------------------------------
// Helpers
// ---------------------------------------------------------------------------
__device__ __forceinline__ uint32_t smem_u32(const void* p) {
    uint32_t a;
    asm("{ .reg .u64 t; cvta.to.shared.u64 t, %1; cvt.u32.u64 %0, t; }"
        : "=r"(a) : "l"(p));
    return a;
}

__device__ __forceinline__ void cp16(uint32_t dst_smem, const void* src_gmem) {
    asm volatile("cp.async.cg.shared.global [%0], [%1], 16;"
                 :: "r"(dst_smem), "l"(__cvta_generic_to_global(src_gmem)));
}
#define CP_COMMIT() asm volatile("cp.async.commit_group;" ::: "memory")
#define CP_WAIT1()  asm volatile("cp.async.wait_group 1;"  ::: "memory")

// ldmatrix x4 (non-transposed, b16)
__device__ __forceinline__ void ldsm4(uint32_t* r, uint32_t addr) {
    asm volatile("ldmatrix.sync.aligned.m8n8.x4.shared.b16 {%0,%1,%2,%3}, [%4];"
                 : "=r"(r[0]), "=r"(r[1]), "=r"(r[2]), "=r"(r[3]) : "r"(addr));
}

// m16n8k16 fp16 -> fp32 accumulate
__device__ __forceinline__ void mma16816(float* c,
                                         uint32_t a0, uint32_t a1, uint32_t a2, uint32_t a3,
                                         uint32_t b0, uint32_t b1) {
    asm volatile(
        "mma.sync.aligned.m16n8k16.row.col.f32.f16.f16.f32 "
        "{%0,%1,%2,%3}, {%4,%5,%6,%7}, {%8,%9}, {%0,%1,%2,%3};"
        : "+f"(c[0]), "+f"(c[1]), "+f"(c[2]), "+f"(c[3])
        : "r"(a0), "r"(a1), "r"(a2), "r"(a3), "r"(b0), "r"(b1));
}

// ---------------------------------------------------------------------------
// Fused convert: fp32 -> fp16, 3 arrays per launch (z).
// ---------------------------------------------------------------------------
struct CvtArgs {
    const float* src[3];
    __half* dst[3];
    size_t n;
};

__global__ __launch_bounds__(256)
void convert3_kernel(CvtArgs a)
{
    const int z = blockIdx.z;
    const float* __restrict__ x = a.src[z];
    __half* __restrict__ d = a.dst[z];
    const size_t n = a.n;
    const size_t stride = (size_t)gridDim.x * blockDim.x * 8;

    for (size_t i = ((size_t)blockIdx.x * blockDim.x + threadIdx.x) * 8;
         i < n; i += stride) {
#pragma unroll
        for (int w = 0; w < 2; w++) {
            float4 v = *(const float4*)(x + i + w * 4);
            __half2* pd = (__half2*)(d + i + w * 4);
            pd[0] = __halves2half2(__float2half_rn(v.x), __float2half_rn(v.y));
            pd[1] = __halves2half2(__float2half_rn(v.z), __float2half_rn(v.w));
        }
    }
}

// ---------------------------------------------------------------------------
// FP16 NT GEMM on tensor cores (single pass, fp32 accumulate):
//   C[M,N] = alpha * Ah[M,K] * Bh[N,K]^T
// CTA: 128x128x64, 256 threads = 8 warps (4 x 2), warp tile 32x64.
// __launch_bounds__(256, 2): regs capped at 128 so TWO CTAs co-reside
// per SM (2 x 110.6KB smem fits 228KB) -> 4 warps/SMSP with the low
// 192B-per-HMMA smem traffic of the 32x64 warp tile.
// SMEM: 3 stages x 2 tiles (Ah, Bh), each 128 rows x 144B (128B data).
// OUT_MODE 0: fp32 C.  2: fp16 Ch.
// Requires M%128==0, N%128==0, K%64==0.
// ---------------------------------------------------------------------------
#define SROW 144
#define TILE_B (128 * SROW)            // 18432
#define STAGE_B (2 * TILE_B)           // 36864
#define GEMM_SMEM (3 * STAGE_B)        // 110592

template <int OUT_MODE>
__global__ __launch_bounds__(256, 2)
void gemm_f16_nt(const __half* __restrict__ Ah, const __half* __restrict__ Bh,
                 float* __restrict__ C, __half* __restrict__ Ch,
                 int M, int N, int K, float alpha,
                 size_t sA, size_t sB, size_t sC)
{
    extern __shared__ __align__(128) char smem[];
    const uint32_t sb = smem_u32(smem);

    const int tid  = threadIdx.x;
    const int wid  = tid >> 5;
    const int lane = tid & 31;
    const int wm   = wid >> 1;          // 0..3  (M: 4 x 32)
    const int wn   = wid & 1;           // 0..1  (N: 2 x 64)
    const int g    = lane >> 2;         // 0..7
    const int i4   = lane & 3;          // 0..3

    const size_t z = blockIdx.z;
    const __half* pAh = Ah + z * sA;
    const __half* pBh = Bh + z * sB;

    const int aRow0 = blockIdx.y * 128;
    const int bRow0 = blockIdx.x * 128;

    // cp.async indices: 4 iterations cover 128 rows x 8 quarters per tile
    const int cr = tid >> 3;             // rows 0..31 (+32j)
    const int cq = tid & 7;              // 16B quarter 0..7

    // ldmatrix per-lane address offsets
    const int lmA = lane & 15;
    const int lqA = (lane >> 4) & 1;
    uint32_t aoff[2];
#pragma unroll
    for (int fm = 0; fm < 2; fm++)
        aoff[fm] = (uint32_t)((wm * 32 + fm * 16 + lmA) * SROW + lqA * 16);
    const int bn = (lane & 7) + ((lane >> 4) << 3);
    const int bq = (lane >> 3) & 1;
    uint32_t boff[4];
#pragma unroll
    for (int fp = 0; fp < 4; fp++)
        boff[fp] = (uint32_t)((wn * 64 + fp * 16 + bn) * SROW + bq * 16);

    float acc[2][8][4];
#pragma unroll
    for (int a = 0; a < 2; a++)
#pragma unroll
        for (int b = 0; b < 8; b++)
#pragma unroll
            for (int c = 0; c < 4; c++) acc[a][b][c] = 0.0f;

    const int nch = K >> 6;

    auto issue = [&](int kc) {
        const uint32_t tb = sb + (uint32_t)(kc % 3) * STAGE_B;
        const int kofs = kc << 6;
#pragma unroll
        for (int j = 0; j < 4; j++) {
            const int r = cr + j * 32;
            const uint32_t so = (uint32_t)(r * SROW + cq * 16);
            cp16(tb + 0 * TILE_B + so, pAh + (size_t)(aRow0 + r) * K + kofs + cq * 8);
            cp16(tb + 1 * TILE_B + so, pBh + (size_t)(bRow0 + r) * K + kofs + cq * 8);
        }
        CP_COMMIT();
    };

    issue(0);
    issue(1);

    for (int kc = 0; kc < nch; kc++) {
        CP_WAIT1();
        __syncthreads();
        if (kc + 2 < nch) issue(kc + 2);

        const uint32_t tb = sb + (uint32_t)(kc % 3) * STAGE_B;
#pragma unroll
        for (int h = 0; h < 4; h++) {
            const uint32_t ho = (uint32_t)(h * 32);
            uint32_t ah[2][4];
#pragma unroll
            for (int fm = 0; fm < 2; fm++)
                ldsm4(ah[fm], tb + 0 * TILE_B + aoff[fm] + ho);
            uint32_t bh[4][4];
#pragma unroll
            for (int fp = 0; fp < 4; fp++)
                ldsm4(bh[fp], tb + 1 * TILE_B + boff[fp] + ho);
#pragma unroll
            for (int fn = 0; fn < 8; fn++) {
                const uint32_t b0 = bh[fn >> 1][(fn & 1) * 2];
                const uint32_t b1 = bh[fn >> 1][(fn & 1) * 2 + 1];
#pragma unroll
                for (int fm = 0; fm < 2; fm++)
                    mma16816(acc[fm][fn], ah[fm][0], ah[fm][1], ah[fm][2], ah[fm][3], b0, b1);
            }
        }
    }

    // Epilogue
    const int rowB = aRow0 + wm * 32 + g;
    const int colB = bRow0 + wn * 64 + i4 * 2;
#pragma unroll
    for (int fm = 0; fm < 2; fm++) {
#pragma unroll
        for (int fn = 0; fn < 8; fn++) {
            const int row = rowB + fm * 16;
            const int col = colB + fn * 8;
            const float c0 = alpha * acc[fm][fn][0];
            const float c1 = alpha * acc[fm][fn][1];
            const float c2 = alpha * acc[fm][fn][2];
            const float c3 = alpha * acc[fm][fn][3];
            if (OUT_MODE == 0) {
                float* pc = C + z * sC;
                *(float2*)(pc + (size_t)row * N + col)       = make_float2(c0, c1);
                *(float2*)(pc + (size_t)(row + 8) * N + col) = make_float2(c2, c3);
            } else {
                __half* ph = Ch + z * sC;
                *(__half2*)(ph + (size_t)row * N + col) =
                    __halves2half2(__float2half_rn(c0), __float2half_rn(c1));
                *(__half2*)(ph + (size_t)(row + 8) * N + col) =
                    __halves2half2(__float2half_rn(c2), __float2half_rn(c3));
            }
        }
    }
}

// ---------------------------------------------------------------------------
// Transpose fp16: V[b][s][o] -> VT[b][o][s] (32x32 tiles)
// ---------------------------------------------------------------------------
__global__ __launch_bounds__(256)
void transpose_h_kernel(const __half* __restrict__ V, __half* __restrict__ T)
{
    __shared__ uint16_t t[32][34];
    const int b  = blockIdx.z;
    const int s0 = blockIdx.x << 5;
    const int o0 = blockIdx.y << 5;
    const __half* Vb = V + (size_t)b * TT * EE;
    __half* Tb = T + (size_t)b * EE * TT;
    const int tx = threadIdx.x & 31;
    const int ty = threadIdx.x >> 5;
#pragma unroll
    for (int i = 0; i < 4; i++)
        t[ty + 8 * i][tx] = __half_as_ushort(Vb[(size_t)(s0 + ty + 8 * i) * EE + o0 + tx]);
    __syncthreads();
#pragma unroll
    for (int i = 0; i < 4; i++)
        Tb[(size_t)(o0 + ty + 8 * i) * TT + s0 + tx] = __ushort_as_half(t[tx][ty + 8 * i]);
}

// ---------------------------------------------------------------------------
// Masked row softmax: S[B*T, T] fp32 -> fp16 P. mask 0 -> -inf.
// ---------------------------------------------------------------------------
__global__ __launch_bounds__(256)
void softmax_h_kernel(const float* __restrict__ S, const int* __restrict__ mask,
                      __half* __restrict__ Ph)
{
    const int row = blockIdx.x;
    const int t   = row & (TT - 1);
    const float* Srow = S + (size_t)row * TT;
    const int* mrow = mask + (size_t)t * TT;
    const int tid = threadIdx.x;

    float v[8];
    float m = -CUDART_INF_F;
#pragma unroll
    for (int i = 0; i < 8; i++) {
        int s = tid + i * 256;
        float x = (mrow[s] != 0) ? Srow[s] : -CUDART_INF_F;
        v[i] = x;
        m = fmaxf(m, x);
    }

    __shared__ float red[256];
    red[tid] = m;
    __syncthreads();
    for (int off = 128; off > 0; off >>= 1) {
        if (tid < off) red[tid] = fmaxf(red[tid], red[tid + off]);
        __syncthreads();
    }
    m = red[0];
    __syncthreads();

    float sum = 0.0f;
#pragma unroll
    for (int i = 0; i < 8; i++) {
        float e = __expf(v[i] - m);
        v[i] = e;
        sum += e;
    }
    red[tid] = sum;
    __syncthreads();
    for (int off = 128; off > 0; off >>= 1) {
        if (tid < off) red[tid] += red[tid + off];
        __syncthreads();
    }
    const float inv = 1.0f / red[0];

    __half* Phr = Ph + (size_t)row * TT;
#pragma unroll
    for (int i = 0; i < 8; i++)
        Phr[tid + i * 256] = __float2half_rn(v[i] * inv);
}

// ---------------------------------------------------------------------------
// kernel_launch
// Order: 1 convert3(q,k,v)  2 convert3(W)  3 projQ  4 projK  5 projV
//        6 scores GEMM      7 transpose    8 softmax  9 PV GEMM
// ---------------------------------------------------------------------------
extern "C" void kernel_launch(void* const* d_in, const int* in_sizes, int n_in,
                              void* d_out, int out_size)
{
    const float* q    = (const float*)d_in[0];
    const float* k    = (const float*)d_in[1];
    const float* v    = (const float*)d_in[2];
    const int*   mask = (const int*)  d_in[3];
    const float* Wq   = (const float*)d_in[4];
    const float* Wk   = (const float*)d_in[5];
    const float* Wv   = (const float*)d_in[6];
    float* out = (float*)d_out;

    __half *qh, *kh, *vh, *wqh, *wkh, *wvh;
    __half *Qh, *Kh, *Vh, *VTh, *Ph;
    float *S;
    cudaGetSymbolAddress((void**)&qh,  g_qh);
    cudaGetSymbolAddress((void**)&kh,  g_kh);
    cudaGetSymbolAddress((void**)&vh,  g_vh);
    cudaGetSymbolAddress((void**)&wqh, g_Wqh);
    cudaGetSymbolAddress((void**)&wkh, g_Wkh);
    cudaGetSymbolAddress((void**)&wvh, g_Wvh);
    cudaGetSymbolAddress((void**)&Qh,  g_Qh);
    cudaGetSymbolAddress((void**)&Kh,  g_Kh);
    cudaGetSymbolAddress((void**)&Vh,  g_Vh);
    cudaGetSymbolAddress((void**)&VTh, g_VTh);
    cudaGetSymbolAddress((void**)&Ph,  g_Ph);
    cudaGetSymbolAddress((void**)&S,   g_S);

    cudaFuncSetAttribute((const void*)gemm_f16_nt<0>,
                         cudaFuncAttributeMaxDynamicSharedMemorySize, GEMM_SMEM);
    cudaFuncSetAttribute((const void*)gemm_f16_nt<2>,
                         cudaFuncAttributeMaxDynamicSharedMemorySize, GEMM_SMEM);

    const int M = BB * TT;                   // 16384
    const size_t strQKV = (size_t)TT * EE;
    const size_t strS   = (size_t)TT * TT;
    const size_t strVT  = (size_t)EE * TT;

    // 1) Convert q,k,v inputs to fp16
    {
        CvtArgs a;
        a.src[0] = q;  a.src[1] = k;  a.src[2] = v;
        a.dst[0] = qh; a.dst[1] = kh; a.dst[2] = vh;
        a.n = NQKV;
        dim3 gs((unsigned)(NQKV / (256 * 8)), 1, 3);
        convert3_kernel<<<gs, 256>>>(a);
    }
    // 2) Convert weights to fp16
    {
        CvtArgs a;
        a.src[0] = Wq;  a.src[1] = Wk;  a.src[2] = Wv;
        a.dst[0] = wqh; a.dst[1] = wkh; a.dst[2] = wvh;
        a.n = (size_t)EE * EE;
        dim3 gs((unsigned)((size_t)EE * EE / (256 * 8)), 1, 3);
        convert3_kernel<<<gs, 256>>>(a);
    }

    // 3-5) Projections (M=16384, N=1024, K=1024) -> fp16
    dim3 gProj(EE / 128, M / 128, 1);
    gemm_f16_nt<2><<<gProj, 256, GEMM_SMEM>>>(qh, wqh, nullptr, Qh,
        M, EE, EE, 1.0f, 0, 0, 0);
    gemm_f16_nt<2><<<gProj, 256, GEMM_SMEM>>>(kh, wkh, nullptr, Kh,
        M, EE, EE, 1.0f, 0, 0, 0);
    gemm_f16_nt<2><<<gProj, 256, GEMM_SMEM>>>(vh, wvh, nullptr, Vh,
        M, EE, EE, 1.0f, 0, 0, 0);

    // 6) Scores: S_b = (Q_b K_b^T) / 32   (M=N=2048, K=1024, batched) -> fp32
    dim3 gScore(TT / 128, TT / 128, BB);
    gemm_f16_nt<0><<<gScore, 256, GEMM_SMEM>>>(Qh, Kh, S, nullptr,
        TT, TT, EE, 1.0f / 32.0f, strQKV, strQKV, strS);

    // 7) Transpose V (fp16) -> VT
    dim3 gT(TT / 32, EE / 32, BB);
    transpose_h_kernel<<<gT, 256>>>(Vh, VTh);

    // 8) Masked softmax -> fp16 P
    softmax_h_kernel<<<BB * TT, 256>>>(S, mask, Ph);

    // 9) Output: O_b = P_b VT_b^T  (M=2048, N=1024, K=2048, batched) -> fp32
    dim3 gOut(EE / 128, TT / 128, BB);
    gemm_f16_nt<0><<<gOut, 256, GEMM_SMEM>>>(Ph, VTh, out, nullptr,
        TT, EE, TT, 1.0f, strS, strVT, strQKV);
}

// round 13
// speedup vs baseline: 1.2383x; 1.0078x over previous
#include <cuda_runtime.h>
#include <cuda_fp16.h>
#include <math_constants.h>
#include <cstdint>

// Problem constants
#define BB 8
#define TT 2048
#define EE 1024
#define NQKV ((size_t)BB * TT * EE)   // 16,777,216
#define NS   ((size_t)BB * TT * TT)   // 33,554,432

// ---------------------------------------------------------------------------
// Scratch (device globals; allocation forbidden in kernel_launch)
// ---------------------------------------------------------------------------
__device__ __half   g_in2[2 * NQKV];            // q fp16 | k fp16 (adjacent)
__device__ __half   g_vh[NQKV];                 // v input fp16
__device__ __half   g_W2[2 * EE * EE];          // Wq | Wk (adjacent)
__device__ __half   g_Wvh[EE * EE];             // Wv
__device__ __half   g_QK[2 * NQKV];             // Q | K projected (adjacent)
__device__ __half   g_VT[NQKV];                 // V^T: [o][b*TT+s], ld 16384
__device__ float    g_S[NS];                    // scores
__device__ __half   g_Ph[NS];                   // softmax weights (A in PV)
__device__ uint32_t g_maskbits[TT * (TT / 32)]; // mask row bitmask

// ---------------------------------------------------------------------------
// Helpers
// ---------------------------------------------------------------------------
__device__ __forceinline__ uint32_t smem_u32(const void* p) {
    uint32_t a;
    asm("{ .reg .u64 t; cvta.to.shared.u64 t, %1; cvt.u32.u64 %0, t; }"
        : "=r"(a) : "l"(p));
    return a;
}

__device__ __forceinline__ void cp16(uint32_t dst_smem, const void* src_gmem) {
    asm volatile("cp.async.cg.shared.global [%0], [%1], 16;"
                 :: "r"(dst_smem), "l"(__cvta_generic_to_global(src_gmem)));
}
#define CP_COMMIT() asm volatile("cp.async.commit_group;" ::: "memory")
#define CP_WAIT1()  asm volatile("cp.async.wait_group 1;"  ::: "memory")

// ldmatrix x4 (non-transposed, b16)
__device__ __forceinline__ void ldsm4(uint32_t* r, uint32_t addr) {
    asm volatile("ldmatrix.sync.aligned.m8n8.x4.shared.b16 {%0,%1,%2,%3}, [%4];"
                 : "=r"(r[0]), "=r"(r[1]), "=r"(r[2]), "=r"(r[3]) : "r"(addr));
}

// m16n8k16 fp16 -> fp32 accumulate
__device__ __forceinline__ void mma16816(float* c,
                                         uint32_t a0, uint32_t a1, uint32_t a2, uint32_t a3,
                                         uint32_t b0, uint32_t b1) {
    asm volatile(
        "mma.sync.aligned.m16n8k16.row.col.f32.f16.f16.f32 "
        "{%0,%1,%2,%3}, {%4,%5,%6,%7}, {%8,%9}, {%0,%1,%2,%3};"
        : "+f"(c[0]), "+f"(c[1]), "+f"(c[2]), "+f"(c[3])
        : "r"(a0), "r"(a1), "r"(a2), "r"(a3), "r"(b0), "r"(b1));
}

// ---------------------------------------------------------------------------
// Fused convert: fp32 -> fp16, 3 arrays per launch (z).
// ---------------------------------------------------------------------------
struct CvtArgs {
    const float* src[3];
    __half* dst[3];
    size_t n;
};

__global__ __launch_bounds__(256)
void convert3_kernel(CvtArgs a)
{
    const int z = blockIdx.z;
    const float* __restrict__ x = a.src[z];
    __half* __restrict__ d = a.dst[z];
    const size_t n = a.n;
    const size_t stride = (size_t)gridDim.x * blockDim.x * 8;

    for (size_t i = ((size_t)blockIdx.x * blockDim.x + threadIdx.x) * 8;
         i < n; i += stride) {
#pragma unroll
        for (int w = 0; w < 2; w++) {
            float4 v = *(const float4*)(x + i + w * 4);
            __half2* pd = (__half2*)(d + i + w * 4);
            pd[0] = __halves2half2(__float2half_rn(v.x), __float2half_rn(v.y));
            pd[1] = __halves2half2(__float2half_rn(v.z), __float2half_rn(v.w));
        }
    }
}

// ---------------------------------------------------------------------------
// Mask -> bitmask: bits[t][w] bit j = (mask[t][w*32+j] != 0)
// ---------------------------------------------------------------------------
__global__ __launch_bounds__(64)
void maskbits_kernel(const int* __restrict__ mask, uint32_t* __restrict__ bits)
{
    const int t = blockIdx.x;
    const int w = threadIdx.x;                 // 0..63
    const int* row = mask + (size_t)t * TT + w * 32;
    uint32_t b = 0;
#pragma unroll
    for (int j = 0; j < 32; j++)
        b |= (row[j] != 0 ? 1u : 0u) << j;
    bits[t * (TT / 32) + w] = b;
}

// ---------------------------------------------------------------------------
// FP16 NT GEMM on tensor cores (single pass, fp32 accumulate):
//   C[M,N] = alpha * Ah[M,K] * Bh[N,K]^T
// A row stride = K; B row stride = ldB; C row stride = ldC.
// CTA: 128x128x64, 256 threads = 8 warps (4 x 2), warp tile 32x64.
// __launch_bounds__(256, 2): two CTAs co-reside per SM (regs<=128,
// 2 x 110.6KB smem) -> 4 warps/SMSP with 192B-per-HMMA smem traffic.
// SMEM: 3 stages x 2 tiles (Ah, Bh), each 128 rows x 144B (128B data).
// OUT_MODE 0: fp32 C.  2: fp16 Ch.
// Requires M%128==0, N%128==0, K%64==0.
// ---------------------------------------------------------------------------
#define SROW 144
#define TILE_B (128 * SROW)            // 18432
#define STAGE_B (2 * TILE_B)           // 36864
#define GEMM_SMEM (3 * STAGE_B)        // 110592

template <int OUT_MODE>
__global__ __launch_bounds__(256, 2)
void gemm_f16_nt(const __half* __restrict__ Ah, const __half* __restrict__ Bh,
                 float* __restrict__ C, __half* __restrict__ Ch,
                 int M, int N, int K, int ldB, int ldC, float alpha,
                 size_t sA, size_t sB, size_t sC)
{
    extern __shared__ __align__(128) char smem[];
    const uint32_t sb = smem_u32(smem);

    const int tid  = threadIdx.x;
    const int wid  = tid >> 5;
    const int lane = tid & 31;
    const int wm   = wid >> 1;          // 0..3  (M: 4 x 32)
    const int wn   = wid & 1;           // 0..1  (N: 2 x 64)
    const int g    = lane >> 2;         // 0..7
    const int i4   = lane & 3;          // 0..3

    const size_t z = blockIdx.z;
    const __half* pAh = Ah + z * sA;
    const __half* pBh = Bh + z * sB;

    const int aRow0 = blockIdx.y * 128;
    const int bRow0 = blockIdx.x * 128;

    // cp.async indices: 4 iterations cover 128 rows x 8 quarters per tile
    const int cr = tid >> 3;             // rows 0..31 (+32j)
    const int cq = tid & 7;              // 16B quarter 0..7

    // ldmatrix per-lane address offsets
    const int lmA = lane & 15;
    const int lqA = (lane >> 4) & 1;
    uint32_t aoff[2];
#pragma unroll
    for (int fm = 0; fm < 2; fm++)
        aoff[fm] = (uint32_t)((wm * 32 + fm * 16 + lmA) * SROW + lqA * 16);
    const int bn = (lane & 7) + ((lane >> 4) << 3);
    const int bq = (lane >> 3) & 1;
    uint32_t boff[4];
#pragma unroll
    for (int fp = 0; fp < 4; fp++)
        boff[fp] = (uint32_t)((wn * 64 + fp * 16 + bn) * SROW + bq * 16);

    float acc[2][8][4];
#pragma unroll
    for (int a = 0; a < 2; a++)
#pragma unroll
        for (int b = 0; b < 8; b++)
#pragma unroll
            for (int c = 0; c < 4; c++) acc[a][b][c] = 0.0f;

    const int nch = K >> 6;

    auto issue = [&](int kc) {
        const uint32_t tb = sb + (uint32_t)(kc % 3) * STAGE_B;
        const int kofs = kc << 6;
#pragma unroll
        for (int j = 0; j < 4; j++) {
            const int r = cr + j * 32;
            const uint32_t so = (uint32_t)(r * SROW + cq * 16);
            cp16(tb + 0 * TILE_B + so, pAh + (size_t)(aRow0 + r) * K   + kofs + cq * 8);
            cp16(tb + 1 * TILE_B + so, pBh + (size_t)(bRow0 + r) * ldB + kofs + cq * 8);
        }
        CP_COMMIT();
    };

    issue(0);
    issue(1);

    for (int kc = 0; kc < nch; kc++) {
        CP_WAIT1();
        __syncthreads();
        if (kc + 2 < nch) issue(kc + 2);

        const uint32_t tb = sb + (uint32_t)(kc % 3) * STAGE_B;
#pragma unroll
        for (int h = 0; h < 4; h++) {
            const uint32_t ho = (uint32_t)(h * 32);
            uint32_t ah[2][4];
#pragma unroll
            for (int fm = 0; fm < 2; fm++)
                ldsm4(ah[fm], tb + 0 * TILE_B + aoff[fm] + ho);
            uint32_t bh[4][4];
#pragma unroll
            for (int fp = 0; fp < 4; fp++)
                ldsm4(bh[fp], tb + 1 * TILE_B + boff[fp] + ho);
#pragma unroll
            for (int fn = 0; fn < 8; fn++) {
                const uint32_t b0 = bh[fn >> 1][(fn & 1) * 2];
                const uint32_t b1 = bh[fn >> 1][(fn & 1) * 2 + 1];
#pragma unroll
                for (int fm = 0; fm < 2; fm++)
                    mma16816(acc[fm][fn], ah[fm][0], ah[fm][1], ah[fm][2], ah[fm][3], b0, b1);
            }
        }
    }

    // Epilogue
    const int rowB = aRow0 + wm * 32 + g;
    const int colB = bRow0 + wn * 64 + i4 * 2;
#pragma unroll
    for (int fm = 0; fm < 2; fm++) {
#pragma unroll
        for (int fn = 0; fn < 8; fn++) {
            const int row = rowB + fm * 16;
            const int col = colB + fn * 8;
            const float c0 = alpha * acc[fm][fn][0];
            const float c1 = alpha * acc[fm][fn][1];
            const float c2 = alpha * acc[fm][fn][2];
            const float c3 = alpha * acc[fm][fn][3];
            if (OUT_MODE == 0) {
                float* pc = C + z * sC;
                *(float2*)(pc + (size_t)row * ldC + col)       = make_float2(c0, c1);
                *(float2*)(pc + (size_t)(row + 8) * ldC + col) = make_float2(c2, c3);
            } else {
                __half* ph = Ch + z * sC;
                *(__half2*)(ph + (size_t)row * ldC + col) =
                    __halves2half2(__float2half_rn(c0), __float2half_rn(c1));
                *(__half2*)(ph + (size_t)(row + 8) * ldC + col) =
                    __halves2half2(__float2half_rn(c2), __float2half_rn(c3));
            }
        }
    }
}

// ---------------------------------------------------------------------------
// Masked row softmax: S[B*T, T] fp32 -> fp16 P. bitmask 0 -> -inf.
// ---------------------------------------------------------------------------
__global__ __launch_bounds__(256)
void softmax_h_kernel(const float* __restrict__ S,
                      const uint32_t* __restrict__ bits,
                      __half* __restrict__ Ph)
{
    const int row = blockIdx.x;
    const int t   = row & (TT - 1);
    const float* Srow = S + (size_t)row * TT;
    const int tid = threadIdx.x;

    __shared__ uint32_t mb[TT / 32];          // 64 words = this row's mask
    if (tid < TT / 32) mb[tid] = bits[t * (TT / 32) + tid];
    __syncthreads();

    float v[8];
    float m = -CUDART_INF_F;
#pragma unroll
    for (int i = 0; i < 8; i++) {
        int s = tid + i * 256;
        bool keep = (mb[s >> 5] >> (s & 31)) & 1u;
        float x = keep ? Srow[s] : -CUDART_INF_F;
        v[i] = x;
        m = fmaxf(m, x);
    }

    __shared__ float red[256];
    red[tid] = m;
    __syncthreads();
    for (int off = 128; off > 0; off >>= 1) {
        if (tid < off) red[tid] = fmaxf(red[tid], red[tid + off]);
        __syncthreads();
    }
    m = red[0];
    __syncthreads();

    float sum = 0.0f;
#pragma unroll
    for (int i = 0; i < 8; i++) {
        float e = __expf(v[i] - m);
        v[i] = e;
        sum += e;
    }
    red[tid] = sum;
    __syncthreads();
    for (int off = 128; off > 0; off >>= 1) {
        if (tid < off) red[tid] += red[tid + off];
        __syncthreads();
    }
    const float inv = 1.0f / red[0];

    __half* Phr = Ph + (size_t)row * TT;
#pragma unroll
    for (int i = 0; i < 8; i++)
        Phr[tid + i * 256] = __float2half_rn(v[i] * inv);
}

// ---------------------------------------------------------------------------
// kernel_launch
// Order: 1 convert3(q,k,v)  2 convert3(Wq,Wk,Wv)  3 projQK (batched z=2)
//        4 projVT (swapped operands -> V^T directly)  5 maskbits
//        6 scores GEMM (profiled slot)  7 softmax  8 PV GEMM
// ---------------------------------------------------------------------------
extern "C" void kernel_launch(void* const* d_in, const int* in_sizes, int n_in,
                              void* d_out, int out_size)
{
    const float* q    = (const float*)d_in[0];
    const float* k    = (const float*)d_in[1];
    const float* v    = (const float*)d_in[2];
    const int*   mask = (const int*)  d_in[3];
    const float* Wq   = (const float*)d_in[4];
    const float* Wk   = (const float*)d_in[5];
    const float* Wv   = (const float*)d_in[6];
    float* out = (float*)d_out;

    __half *in2, *vh, *W2, *wvh, *QK, *VT, *Ph;
    float *S;
    uint32_t *mbits;
    cudaGetSymbolAddress((void**)&in2,  g_in2);
    cudaGetSymbolAddress((void**)&vh,   g_vh);
    cudaGetSymbolAddress((void**)&W2,   g_W2);
    cudaGetSymbolAddress((void**)&wvh,  g_Wvh);
    cudaGetSymbolAddress((void**)&QK,   g_QK);
    cudaGetSymbolAddress((void**)&VT,   g_VT);
    cudaGetSymbolAddress((void**)&Ph,   g_Ph);
    cudaGetSymbolAddress((void**)&S,    g_S);
    cudaGetSymbolAddress((void**)&mbits, g_maskbits);

    cudaFuncSetAttribute((const void*)gemm_f16_nt<0>,
                         cudaFuncAttributeMaxDynamicSharedMemorySize, GEMM_SMEM);
    cudaFuncSetAttribute((const void*)gemm_f16_nt<2>,
                         cudaFuncAttributeMaxDynamicSharedMemorySize, GEMM_SMEM);

    const int M = BB * TT;                   // 16384
    const size_t strQKV = (size_t)TT * EE;
    const size_t strS   = (size_t)TT * TT;

    // 1) Convert q,k,v inputs to fp16 (q,k packed adjacent)
    {
        CvtArgs a;
        a.src[0] = q;    a.src[1] = k;           a.src[2] = v;
        a.dst[0] = in2;  a.dst[1] = in2 + NQKV;  a.dst[2] = vh;
        a.n = NQKV;
        dim3 gs((unsigned)(NQKV / (256 * 8)), 1, 3);
        convert3_kernel<<<gs, 256>>>(a);
    }
    // 2) Convert weights to fp16 (Wq,Wk packed adjacent)
    {
        CvtArgs a;
        a.src[0] = Wq;  a.src[1] = Wk;                a.src[2] = Wv;
        a.dst[0] = W2;  a.dst[1] = W2 + (size_t)EE * EE;  a.dst[2] = wvh;
        a.n = (size_t)EE * EE;
        dim3 gs((unsigned)((size_t)EE * EE / (256 * 8)), 1, 3);
        convert3_kernel<<<gs, 256>>>(a);
    }

    // 3) Q and K projections in ONE batched launch (z = 0:Q, 1:K)
    //    Q|K = (q|k) @ (Wq|Wk)^T   (M=16384, N=1024, K=1024)
    {
        dim3 gProj(EE / 128, M / 128, 2);
        gemm_f16_nt<2><<<gProj, 256, GEMM_SMEM>>>(in2, W2, nullptr, QK,
            M, EE, EE, /*ldB=*/EE, /*ldC=*/EE, 1.0f,
            /*sA=*/NQKV, /*sB=*/(size_t)EE * EE, /*sC=*/NQKV);
    }

    // 4) V^T projection via swapped operands:
    //    VT[o][gs] = sum_e Wv[o][e] * v[gs][e]   (M=1024, N=16384, ldC=16384)
    {
        dim3 gVT(M / 128, EE / 128, 1);
        gemm_f16_nt<2><<<gVT, 256, GEMM_SMEM>>>(wvh, vh, nullptr, VT,
            EE, M, EE, /*ldB=*/EE, /*ldC=*/M, 1.0f, 0, 0, 0);
    }

    // 5) Mask -> bitmask (one-time, 512KB)
    maskbits_kernel<<<TT, 64>>>(mask, mbits);

    // 6) Scores: S_b = (Q_b K_b^T) / 32   (M=N=2048, K=1024, batched)
    {
        dim3 gScore(TT / 128, TT / 128, BB);
        gemm_f16_nt<0><<<gScore, 256, GEMM_SMEM>>>(QK, QK + NQKV, S, nullptr,
            TT, TT, EE, /*ldB=*/EE, /*ldC=*/TT, 1.0f / 32.0f,
            strQKV, strQKV, strS);
    }

    // 7) Masked softmax -> fp16 P
    softmax_h_kernel<<<BB * TT, 256>>>(S, mbits, Ph);

    // 8) Output: O_b = P_b @ VT_b^T  (M=2048, N=1024, K=2048, batched)
    //    B operand = VT + b*2048 (column slice), row stride 16384.
    {
        dim3 gOut(EE / 128, TT / 128, BB);
        gemm_f16_nt<0><<<gOut, 256, GEMM_SMEM>>>(Ph, VT, out, nullptr,
            TT, EE, TT, /*ldB=*/M, /*ldC=*/EE, 1.0f,
            strS, /*sB=*/(size_t)TT, strQKV);
    }
}